// round 12
// baseline (speedup 1.0000x reference)
#include <cuda_runtime.h>
#include <cuda_fp16.h>
#include <math.h>
#include <stdint.h>

// Problem constants (fixed by setup_inputs)
#define BATCH 4
#define TSEQ  8192
#define HDIM  512
#define EDIM  2048
#define CHK   64
#define STR   32
#define NCH   256                     // TSEQ / STR
#define TOK   (BATCH * NCH * CHK)     // 65536
#define LN_EPS 1e-5f

// ---------------- scratch (static device globals; no allocation) ----------
__device__ float g_M[CHK * CHK];
__device__ float g_mu1[TOK];
__device__ float g_rs1[TOK];
__device__ __half g_oc[(size_t)TOK * HDIM];        // 64 MB fp16
__device__ __half g_c2h[(size_t)TOK * HDIM];       // 64 MB fp16 (resid)
__device__ __half g_vn[(size_t)TOK * HDIM];        // 64 MB fp16
__device__ __half g_u [(size_t)TOK * EDIM];        // 256 MB fp16
__device__ __half g_w1[(size_t)EDIM * HDIM];       // fw1^T fp16 [E,H]
__device__ __half g_w2[(size_t)HDIM * EDIM];       // fw2^T fp16 [H,E]

// ---------------- PTX helpers (baseline ISA only: sm_80+) -----------------
__device__ __forceinline__ uint32_t smem_u32(const void* p) {
    uint32_t a;
    asm("{ .reg .u64 t; cvta.to.shared.u64 t, %1; cvt.u32.u64 %0, t; }"
        : "=r"(a) : "l"(p));
    return a;
}
#define CP16(dst, src) \
    asm volatile("cp.async.cg.shared.global [%0], [%1], 16;" :: "r"(dst), "l"(src))
#define CP_COMMIT() asm volatile("cp.async.commit_group;" ::: "memory")

__device__ __forceinline__ void ldsm4(uint32_t* r, uint32_t addr) {
    asm volatile("ldmatrix.sync.aligned.m8n8.x4.shared.b16 {%0,%1,%2,%3}, [%4];"
        : "=r"(r[0]), "=r"(r[1]), "=r"(r[2]), "=r"(r[3]) : "r"(addr));
}
__device__ __forceinline__ void mma16816(float* d, const uint32_t* a, const uint32_t* b) {
    asm volatile("mma.sync.aligned.m16n8k16.row.col.f32.f16.f16.f32 "
        "{%0,%1,%2,%3}, {%4,%5,%6,%7}, {%8,%9}, {%0,%1,%2,%3};"
        : "+f"(d[0]), "+f"(d[1]), "+f"(d[2]), "+f"(d[3])
        : "r"(a[0]), "r"(a[1]), "r"(a[2]), "r"(a[3]), "r"(b[0]), "r"(b[1]));
}

// SW128 swizzle for rows of 128 B (BK=64 fp16), 8x16B segs per row.
__device__ __forceinline__ uint32_t tileOff128(int row, int c16) {
    return (uint32_t)(row * 128 + ((c16 ^ (row & 7)) << 4));
}

// ---------------- prep kernel: combine_w + 2x weight transpose + ln1 ------
#define PREP_LN1_BLKS  (TOK / 8)
#define PREP_TS1_BLKS  ((EDIM / 32) * (HDIM / 32))
#define PREP_TS2_BLKS  ((HDIM / 32) * (EDIM / 32))
#define PREP_CMB_BLKS  (CHK / 4)
#define PREP_BLKS (PREP_LN1_BLKS + PREP_TS1_BLKS + PREP_TS2_BLKS + PREP_CMB_BLKS)

__device__ __forceinline__ void tsplit_body(const float* __restrict__ W,
                                            __half* __restrict__ O,
                                            int R, int C, int bx, int by,
                                            int tid, float (*t)[33]) {
    int c0 = bx * 32, r0 = by * 32;
    int x = tid & 31, y = tid >> 5;
#pragma unroll
    for (int dy = 0; dy < 32; dy += 8)
        t[y + dy][x] = W[(size_t)(r0 + y + dy) * C + c0 + x];
    __syncthreads();
#pragma unroll
    for (int dy = 0; dy < 32; dy += 8)
        O[(size_t)(c0 + y + dy) * R + r0 + x] = __float2half(t[x][y + dy]);
}

__global__ void __launch_bounds__(256) prep_kernel(
    const float* __restrict__ x,
    const float* __restrict__ W1, const float* __restrict__ W2,
    const float* __restrict__ fw1, const float* __restrict__ fw2,
    __half* __restrict__ w1o, __half* __restrict__ w2o) {
    __shared__ float ts[32][33];
    int bid = blockIdx.x, tid = threadIdx.x;
    if (bid < PREP_LN1_BLKS) {
        int warp = tid >> 5, lane = tid & 31;
        int row  = bid * 8 + warp;
        int t = row & (CHK - 1);
        int n = (row >> 6) & (NCH - 1);
        int b = row >> 14;
        int pos = n * STR + t;
        bool valid = pos < TSEQ;
        const float* xr = x + ((size_t)b * TSEQ + (valid ? pos : 0)) * HDIM;
        float sum = 0.f, sq = 0.f;
#pragma unroll
        for (int i = 0; i < HDIM / 32; ++i) {
            float v = valid ? xr[lane + 32 * i] : 0.f;
            sum += v; sq += v * v;
        }
#pragma unroll
        for (int o = 16; o; o >>= 1) {
            sum += __shfl_xor_sync(0xffffffffu, sum, o);
            sq  += __shfl_xor_sync(0xffffffffu, sq,  o);
        }
        if (lane == 0) {
            float m   = sum * (1.f / HDIM);
            float var = fmaxf(sq * (1.f / HDIM) - m * m, 0.f);
            g_mu1[row] = m;
            g_rs1[row] = rsqrtf(var + LN_EPS);
        }
    } else if (bid < PREP_LN1_BLKS + PREP_TS1_BLKS) {
        int b2 = bid - PREP_LN1_BLKS;
        tsplit_body(fw1, w1o, HDIM, EDIM, b2 % (EDIM / 32), b2 / (EDIM / 32),
                    tid, ts);
    } else if (bid < PREP_LN1_BLKS + PREP_TS1_BLKS + PREP_TS2_BLKS) {
        int b2 = bid - PREP_LN1_BLKS - PREP_TS1_BLKS;
        tsplit_body(fw2, w2o, EDIM, HDIM, b2 % (HDIM / 32), b2 / (HDIM / 32),
                    tid, ts);
    } else {
        int b2 = bid - PREP_LN1_BLKS - PREP_TS1_BLKS - PREP_TS2_BLKS;
        int t = b2 * 4 + (tid >> 6);
        int u = tid & 63;
        float s = 0.f;
        for (int k = u; k <= t; ++k)
            s += W2[t * CHK + k] * W1[k * CHK + u];
        g_M[t * CHK + u] = s;
    }
}

// ---- kernel 2: c2 = M @ LN1(chunk) + chunk ; then fused LN2 -> vn --------
#define CM_SMEM_BYTES (16384 + CHK * HDIM * 2)   // As 16KB + tile 64KB
__global__ void __launch_bounds__(512) chunk_mm_kernel(
    const float* __restrict__ x,
    const float* __restrict__ g1, const float* __restrict__ b1,
    const float* __restrict__ g2, const float* __restrict__ b2) {
    extern __shared__ __align__(128) char cm_smem[];
    float*  As  = (float*)cm_smem;                       // 64x64
    __half* c2s = (__half*)(cm_smem + 16384);            // 64x512
    __shared__ float mu_s[CHK], rs_s[CHK], bias_s[CHK], rowm_s[CHK];
    int tid = threadIdx.x;
    int n = blockIdx.x, b = blockIdx.y;
    int tokbase = (b * NCH + n) * CHK;

    if (tid < CHK) { mu_s[tid] = g_mu1[tokbase + tid]; rs_s[tid] = g_rs1[tokbase + tid]; }
    for (int i = tid; i < CHK * CHK; i += 512) As[i] = g_M[i];
    __syncthreads();
    if (tid < CHK) {
        float rm = 0.f;
        for (int u = 0; u < CHK; ++u) rm += As[tid * CHK + u];
        rowm_s[tid] = rm;
    }
    __syncthreads();
    for (int i = tid; i < CHK * CHK; i += 512) As[i] *= rs_s[i & (CHK - 1)];
    __syncthreads();
    if (tid < CHK) {
        float bs = 0.f;
        for (int u = 0; u < CHK; ++u) bs += As[tid * CHK + u] * mu_s[u];
        bias_s[tid] = -bs;
    }
    __syncthreads();

    {   // phase 1
        int h = tid;
        const float* xb = x + (size_t)b * TSEQ * HDIM + h;
        float xcol[CHK];
#pragma unroll
        for (int u = 0; u < CHK; ++u) {
            int pos = n * STR + u;
            xcol[u] = (pos < TSEQ) ? xb[(size_t)pos * HDIM] : 0.f;
        }
        float g1h = g1[h], b1h = b1[h];
        __half* cg = g_c2h + (size_t)tokbase * HDIM + h;
#pragma unroll 2
        for (int t = 0; t < CHK; ++t) {
            float acc = bias_s[t];
            const float4* arow = (const float4*)&As[t * CHK];
#pragma unroll
            for (int u4 = 0; u4 < CHK / 4; ++u4) {
                float4 a = arow[u4];
                acc += a.x * xcol[4 * u4 + 0];
                acc += a.y * xcol[4 * u4 + 1];
                acc += a.z * xcol[4 * u4 + 2];
                acc += a.w * xcol[4 * u4 + 3];
            }
            int pos = n * STR + t;
            float res = (pos < TSEQ) ? xb[(size_t)pos * HDIM] : 0.f;
            __half hv = __float2half(g1h * acc + b1h * rowm_s[t] + res);
            c2s[t * HDIM + h] = hv;
            cg[(size_t)t * HDIM] = hv;
        }
    }
    __syncthreads();

    {   // phase 2: LN2 on rows; warp w handles t = w*4 .. w*4+3
        int w = tid >> 5, lane = tid & 31;
        int h0 = lane * 16;
        float g2v[16], b2v[16];
#pragma unroll
        for (int j = 0; j < 16; ++j) { g2v[j] = g2[h0 + j]; b2v[j] = b2[h0 + j]; }
#pragma unroll
        for (int r = 0; r < 4; ++r) {
            int t = w * 4 + r;
            const uint4* rowp = (const uint4*)(c2s + t * HDIM);
            uint4 d0 = rowp[lane * 2], d1 = rowp[lane * 2 + 1];
            float vv[16];
            {
                const __half2* p0 = (const __half2*)&d0;
                const __half2* p1 = (const __half2*)&d1;
#pragma unroll
                for (int q = 0; q < 4; ++q) {
                    float2 f0 = __half22float2(p0[q]);
                    float2 f1 = __half22float2(p1[q]);
                    vv[2 * q] = f0.x; vv[2 * q + 1] = f0.y;
                    vv[8 + 2 * q] = f1.x; vv[8 + 2 * q + 1] = f1.y;
                }
            }
            float sum = 0.f, sq = 0.f;
#pragma unroll
            for (int j = 0; j < 16; ++j) { sum += vv[j]; sq += vv[j] * vv[j]; }
#pragma unroll
            for (int o = 16; o; o >>= 1) {
                sum += __shfl_xor_sync(0xffffffffu, sum, o);
                sq  += __shfl_xor_sync(0xffffffffu, sq,  o);
            }
            float m   = sum * (1.f / HDIM);
            float var = fmaxf(sq * (1.f / HDIM) - m * m, 0.f);
            float rs  = rsqrtf(var + LN_EPS);
            uint4 o0, o1;
            __half2* q0 = (__half2*)&o0;
            __half2* q1 = (__half2*)&o1;
#pragma unroll
            for (int q = 0; q < 4; ++q) {
                q0[q] = __floats2half2_rn(
                    (vv[2 * q]     - m) * rs * g2v[2 * q]     + b2v[2 * q],
                    (vv[2 * q + 1] - m) * rs * g2v[2 * q + 1] + b2v[2 * q + 1]);
                q1[q] = __floats2half2_rn(
                    (vv[8 + 2 * q]     - m) * rs * g2v[8 + 2 * q]     + b2v[8 + 2 * q],
                    (vv[8 + 2 * q + 1] - m) * rs * g2v[8 + 2 * q + 1] + b2v[8 + 2 * q + 1]);
            }
            uint4* vp = (uint4*)(g_vn + (size_t)(tokbase + t) * HDIM + h0);
            vp[0] = o0; vp[1] = o1;
        }
    }
}

// ---------------- single-pass fp16 HMMA GEMM, block 256x128 ---------------
// C[m,n] = sum_k A[m,k]*B[n,k]; A [M,K], B [N,K] fp16 row-major (K contig).
// Block 256x128, BK=64, 3-stage cp.async pipeline (48 KB/stage, 144 KB),
// 512 threads = 16 warps (4M x 4N), warp tile 64x32. Larger M-block cuts
// smem-crossbar bytes/MMA from 320 to 240 (< 256 B/MMA tensor budget).
// MODE 0: out = __sinf(acc + bias[n]) -> fp16. MODE 1: out = acc+bias+resid fp16.
#define GSTAGES 3
#define GSTAGE_BYTES 49152           // A tile 32KB + B tile 16KB
#define GEMM_SMEM_BYTES (GSTAGES * GSTAGE_BYTES)

template <int MODE>
__global__ void __launch_bounds__(512, 1) gemm_mma(
    const __half* __restrict__ A, const __half* __restrict__ B,
    const float* __restrict__ bias, const __half* __restrict__ resid,
    __half* __restrict__ outH, int K, int N) {
    extern __shared__ __align__(128) char smem[];
    const uint32_t sb = smem_u32(smem);
    const int tid = threadIdx.x;
    const int wid = tid >> 5, lane = tid & 31;
    const int wm = wid & 3;           // M quarter (64 rows)
    const int wn = wid >> 2;          // N quarter (32 cols)
    const size_t mBase = (size_t)blockIdx.y * 256;
    const int    nBase = blockIdx.x * 128;
    const size_t ldbytes = (size_t)K * 2;
    const int KT = K >> 6;            // BK = 64

    // ---- stage loader: A 2048 chunks + B 1024 chunks of 16B, 6/thread ----
    auto load_stage = [&](int kt) {
        const uint32_t stg = sb + (kt % GSTAGES) * GSTAGE_BYTES;
        const size_t kOff = (size_t)kt * 128;   // 64 fp16 = 128 bytes
#pragma unroll
        for (int t = 0; t < 4; ++t) {           // A: 256 rows x 8 c16
            int cc = t * 512 + tid;             // 0..2047
            int row = cc >> 3, c16 = cc & 7;
            uint32_t sdst = stg + tileOff128(row, c16);
            CP16(sdst, (const char*)A + (mBase + row) * ldbytes + kOff + c16 * 16);
        }
#pragma unroll
        for (int t = 0; t < 2; ++t) {           // B: 128 rows x 8 c16
            int cc = t * 512 + tid;             // 0..1023
            int row = cc >> 3, c16 = cc & 7;
            uint32_t sdst = stg + 32768 + tileOff128(row, c16);
            CP16(sdst, (const char*)B + ((size_t)nBase + row) * ldbytes + kOff + c16 * 16);
        }
    };

    float acc[4][4][4];
#pragma unroll
    for (int i = 0; i < 4; ++i)
#pragma unroll
        for (int j = 0; j < 4; ++j)
#pragma unroll
            for (int q = 0; q < 4; ++q) acc[i][j][q] = 0.f;

    load_stage(0); CP_COMMIT();
    if (KT > 1) { load_stage(1); CP_COMMIT(); }

    const int lrow = lane & 15;
    const int lcol = lane >> 4;

    for (int kt = 0; kt < KT; ++kt) {
        if (kt + 1 < KT) asm volatile("cp.async.wait_group 1;" ::: "memory");
        else             asm volatile("cp.async.wait_group 0;" ::: "memory");
        __syncthreads();
        if (kt + 2 < KT) { load_stage(kt + 2); CP_COMMIT(); }

        const uint32_t stg = sb + (kt % GSTAGES) * GSTAGE_BYTES;
        const uint32_t sA = stg, sB = stg + 32768;

#pragma unroll
        for (int ks = 0; ks < 4; ++ks) {
            const int c16 = ks * 2 + lcol;
            uint32_t ah[4][4], bh[4][2];
#pragma unroll
            for (int mi = 0; mi < 4; ++mi)
                ldsm4(ah[mi], sA + tileOff128(wm * 64 + mi * 16 + lrow, c16));
#pragma unroll
            for (int p = 0; p < 2; ++p) {
                uint32_t t4[4];
                ldsm4(t4, sB + tileOff128(wn * 32 + p * 16 + lrow, c16));
                bh[2 * p][0] = t4[0]; bh[2 * p][1] = t4[2];
                bh[2 * p + 1][0] = t4[1]; bh[2 * p + 1][1] = t4[3];
            }
#pragma unroll
            for (int mi = 0; mi < 4; ++mi)
#pragma unroll
                for (int ni = 0; ni < 4; ++ni)
                    mma16816(acc[mi][ni], ah[mi], bh[ni]);
        }
    }

    // ---- epilogue: lane holds rows {g, g+8}, cols {c, c+1} per tile ----
    const int g = lane >> 2, cq = (lane & 3) * 2;
#pragma unroll
    for (int ni = 0; ni < 4; ++ni) {
        const int col = nBase + wn * 32 + ni * 8 + cq;
        const float b0 = bias[col], b1 = bias[col + 1];
#pragma unroll
        for (int mi = 0; mi < 4; ++mi) {
            const size_t r0 = mBase + wm * 64 + mi * 16 + g;
            const size_t r1 = r0 + 8;
            if (MODE == 0) {
                float f00 = __sinf(acc[mi][ni][0] + b0);
                float f01 = __sinf(acc[mi][ni][1] + b1);
                float f10 = __sinf(acc[mi][ni][2] + b0);
                float f11 = __sinf(acc[mi][ni][3] + b1);
                *(__half2*)(outH + r0 * N + col) = __floats2half2_rn(f00, f01);
                *(__half2*)(outH + r1 * N + col) = __floats2half2_rn(f10, f11);
            } else {
                float2 rv0 = __half22float2(*(const __half2*)(resid + r0 * N + col));
                float2 rv1 = __half22float2(*(const __half2*)(resid + r1 * N + col));
                *(__half2*)(outH + r0 * N + col) = __floats2half2_rn(
                    acc[mi][ni][0] + b0 + rv0.x, acc[mi][ni][1] + b1 + rv0.y);
                *(__half2*)(outH + r1 * N + col) = __floats2half2_rn(
                    acc[mi][ni][2] + b0 + rv1.x, acc[mi][ni][3] + b1 + rv1.y);
            }
        }
    }
}

// ---------------- gather: overlap sum + count division (fp16 oc) ----------
__global__ void gather_kernel(float* __restrict__ out) {
    size_t gid = (size_t)blockIdx.x * blockDim.x + threadIdx.x; // B*T*H/8
    int h8 = (int)(gid & (HDIM / 8 - 1));        // 0..63
    size_t rest = gid >> 6;
    int p = (int)(rest & (TSEQ - 1));
    int b = (int)(rest >> 13);
    const uint4* oc8 = (const uint4*)g_oc;       // 8 halves per uint4
    int nn = p >> 5, t = p & 31;
    size_t i0 = ((size_t)(b * NCH + nn) * CHK + t) * (HDIM / 8) + h8;
    uint4 v = oc8[i0];
    const __half2* vh = (const __half2*)&v;
    float r[8];
#pragma unroll
    for (int q = 0; q < 4; ++q) {
        float2 f = __half22float2(vh[q]);
        r[2 * q] = f.x; r[2 * q + 1] = f.y;
    }
    if (p >= STR) {
        size_t i1 = ((size_t)(b * NCH + nn - 1) * CHK + t + 32) * (HDIM / 8) + h8;
        uint4 w = oc8[i1];
        const __half2* wh = (const __half2*)&w;
#pragma unroll
        for (int q = 0; q < 4; ++q) {
            float2 f = __half22float2(wh[q]);
            r[2 * q]     = (r[2 * q]     + f.x) * 0.5f;
            r[2 * q + 1] = (r[2 * q + 1] + f.y) * 0.5f;
        }
    }
    float4* op = (float4*)(out + ((size_t)b * TSEQ + p) * HDIM + h8 * 8);
    op[0] = make_float4(r[0], r[1], r[2], r[3]);
    op[1] = make_float4(r[4], r[5], r[6], r[7]);
}

// ---------------- launch --------------------------------------------------
extern "C" void kernel_launch(void* const* d_in, const int* in_sizes, int n_in,
                              void* d_out, int out_size) {
    const float* x     = (const float*)d_in[0];
    const float* ln1_g = (const float*)d_in[1];
    const float* ln1_b = (const float*)d_in[2];
    const float* W1    = (const float*)d_in[3];
    const float* W2    = (const float*)d_in[4];
    const float* ln2_g = (const float*)d_in[5];
    const float* ln2_b = (const float*)d_in[6];
    const float* fw1   = (const float*)d_in[7];
    const float* fb1   = (const float*)d_in[8];
    const float* fw2   = (const float*)d_in[9];
    const float* fb2   = (const float*)d_in[10];
    float* out = (float*)d_out;

    __half *ocp, *c2hp, *vnp, *up, *w1p, *w2p;
    cudaGetSymbolAddress((void**)&ocp,  g_oc);
    cudaGetSymbolAddress((void**)&c2hp, g_c2h);
    cudaGetSymbolAddress((void**)&vnp,  g_vn);
    cudaGetSymbolAddress((void**)&up,   g_u);
    cudaGetSymbolAddress((void**)&w1p,  g_w1);
    cudaGetSymbolAddress((void**)&w2p,  g_w2);

    cudaFuncSetAttribute(gemm_mma<0>, cudaFuncAttributeMaxDynamicSharedMemorySize,
                         GEMM_SMEM_BYTES);
    cudaFuncSetAttribute(gemm_mma<1>, cudaFuncAttributeMaxDynamicSharedMemorySize,
                         GEMM_SMEM_BYTES);
    cudaFuncSetAttribute(chunk_mm_kernel, cudaFuncAttributeMaxDynamicSharedMemorySize,
                         CM_SMEM_BYTES);

    // 1) prep: ln1 stats + both weight transposes + combined W
    prep_kernel<<<PREP_BLKS, 256>>>(x, W1, W2, fw1, fw2, w1p, w2p);
    // 2) chunk matmul + fused LN2
    chunk_mm_kernel<<<dim3(NCH, BATCH), 512, CM_SMEM_BYTES>>>(
        x, ln1_g, ln1_b, ln2_g, ln2_b);
    // 3) GEMM1: u = sin(vn @ fw1 + fb1)  [65536 x 512] x [2048 x 512]^T
    gemm_mma<0><<<dim3(EDIM / 128, TOK / 256), 512, GEMM_SMEM_BYTES>>>(
        vnp, w1p, fb1, nullptr, up, HDIM, EDIM);
    // 4) GEMM2: oc = u @ fw2 + fb2 + c2  [65536 x 2048] x [512 x 2048]^T
    gemm_mma<1><<<dim3(HDIM / 128, TOK / 256), 512, GEMM_SMEM_BYTES>>>(
        up, w2p, fb2, c2hp, ocp, EDIM, HDIM);
    // 5) overlap gather + divide
    gather_kernel<<<(size_t)BATCH * TSEQ * HDIM / 8 / 256, 256>>>(out);
}

// round 13
// speedup vs baseline: 1.0979x; 1.0979x over previous
#include <cuda_runtime.h>
#include <cuda_fp16.h>
#include <math.h>
#include <stdint.h>

// Problem constants (fixed by setup_inputs)
#define BATCH 4
#define TSEQ  8192
#define HDIM  512
#define EDIM  2048
#define CHK   64
#define STR   32
#define NCH   256                     // TSEQ / STR
#define TOK   (BATCH * NCH * CHK)     // 65536
#define LN_EPS 1e-5f

// ---------------- scratch (static device globals; no allocation) ----------
__device__ float g_M[CHK * CHK];
__device__ __half g_oc[(size_t)TOK * HDIM];        // 64 MB fp16
__device__ __half g_c2h[(size_t)TOK * HDIM];       // 64 MB fp16 (resid)
__device__ __half g_vn[(size_t)TOK * HDIM];        // 64 MB fp16
__device__ __half g_u [(size_t)TOK * EDIM];        // 256 MB fp16
__device__ __half g_w1[(size_t)EDIM * HDIM];       // fw1^T fp16 [E,H]
__device__ __half g_w2[(size_t)HDIM * EDIM];       // fw2^T fp16 [H,E]

// ---------------- PTX helpers (baseline ISA only: sm_80+) -----------------
__device__ __forceinline__ uint32_t smem_u32(const void* p) {
    uint32_t a;
    asm("{ .reg .u64 t; cvta.to.shared.u64 t, %1; cvt.u32.u64 %0, t; }"
        : "=r"(a) : "l"(p));
    return a;
}
#define CP16(dst, src) \
    asm volatile("cp.async.cg.shared.global [%0], [%1], 16;" :: "r"(dst), "l"(src))
#define CP_COMMIT() asm volatile("cp.async.commit_group;" ::: "memory")

__device__ __forceinline__ void ldsm4(uint32_t* r, uint32_t addr) {
    asm volatile("ldmatrix.sync.aligned.m8n8.x4.shared.b16 {%0,%1,%2,%3}, [%4];"
        : "=r"(r[0]), "=r"(r[1]), "=r"(r[2]), "=r"(r[3]) : "r"(addr));
}
__device__ __forceinline__ void mma16816(float* d, const uint32_t* a, const uint32_t* b) {
    asm volatile("mma.sync.aligned.m16n8k16.row.col.f32.f16.f16.f32 "
        "{%0,%1,%2,%3}, {%4,%5,%6,%7}, {%8,%9}, {%0,%1,%2,%3};"
        : "+f"(d[0]), "+f"(d[1]), "+f"(d[2]), "+f"(d[3])
        : "r"(a[0]), "r"(a[1]), "r"(a[2]), "r"(a[3]), "r"(b[0]), "r"(b[1]));
}

// SW128 swizzle for a 128-row x 64-col fp16 tile (128 B rows, 8x16B segs).
__device__ __forceinline__ uint32_t tileOff128(int row, int c16) {
    return (uint32_t)(row * 128 + ((c16 ^ (row & 7)) << 4));
}

// ---------------- prep kernel: combine_w + 2x weight transpose ------------
#define PREP_TS1_BLKS  ((EDIM / 32) * (HDIM / 32))
#define PREP_TS2_BLKS  ((HDIM / 32) * (EDIM / 32))
#define PREP_CMB_BLKS  (CHK / 4)
#define PREP_BLKS (PREP_TS1_BLKS + PREP_TS2_BLKS + PREP_CMB_BLKS)

__device__ __forceinline__ void tsplit_body(const float* __restrict__ W,
                                            __half* __restrict__ O,
                                            int R, int C, int bx, int by,
                                            int tid, float (*t)[33]) {
    int c0 = bx * 32, r0 = by * 32;
    int x = tid & 31, y = tid >> 5;
#pragma unroll
    for (int dy = 0; dy < 32; dy += 8)
        t[y + dy][x] = W[(size_t)(r0 + y + dy) * C + c0 + x];
    __syncthreads();
#pragma unroll
    for (int dy = 0; dy < 32; dy += 8)
        O[(size_t)(c0 + y + dy) * R + r0 + x] = __float2half(t[x][y + dy]);
}

__global__ void __launch_bounds__(256) prep_kernel(
    const float* __restrict__ W1, const float* __restrict__ W2,
    const float* __restrict__ fw1, const float* __restrict__ fw2,
    __half* __restrict__ w1o, __half* __restrict__ w2o) {
    __shared__ float ts[32][33];
    int bid = blockIdx.x, tid = threadIdx.x;
    if (bid < PREP_TS1_BLKS) {
        tsplit_body(fw1, w1o, HDIM, EDIM, bid % (EDIM / 32), bid / (EDIM / 32),
                    tid, ts);
    } else if (bid < PREP_TS1_BLKS + PREP_TS2_BLKS) {
        int b2 = bid - PREP_TS1_BLKS;
        tsplit_body(fw2, w2o, EDIM, HDIM, b2 % (HDIM / 32), b2 / (HDIM / 32),
                    tid, ts);
    } else {
        int b2 = bid - PREP_TS1_BLKS - PREP_TS2_BLKS;
        int t = b2 * 4 + (tid >> 6);
        int u = tid & 63;
        float s = 0.f;
        for (int k = u; k <= t; ++k)
            s += W2[t * CHK + k] * W1[k * CHK + u];
        g_M[t * CHK + u] = s;
    }
}

// ---- kernel 2: fused LN1 stats + c2 = M @ LN1(chunk) + chunk + LN2 -> vn -
// phase 0 : thread h loads x column (64 rows) to regs, stores fp16 tile.
// phase 0b: 16 warps x 4 rows compute LN1 mu/rs from the tile (in-block).
// phase 1 : thread h computes c2 column, stores fp16 tile + global resid.
// phase 2 : 16 warps x 4 rows do LN2 row reductions, write vn (fp16).
#define CM_SMEM_BYTES (16384 + CHK * HDIM * 2)   // As 16KB + tile 64KB
__global__ void __launch_bounds__(512) chunk_mm_kernel(
    const float* __restrict__ x,
    const float* __restrict__ g1, const float* __restrict__ b1,
    const float* __restrict__ g2, const float* __restrict__ b2) {
    extern __shared__ __align__(128) char cm_smem[];
    float*  As  = (float*)cm_smem;                       // 64x64
    __half* c2s = (__half*)(cm_smem + 16384);            // 64x512
    __shared__ float mu_s[CHK], rs_s[CHK], bias_s[CHK], rowm_s[CHK];
    int tid = threadIdx.x;
    int n = blockIdx.x, b = blockIdx.y;
    int tokbase = (b * NCH + n) * CHK;
    const int w = tid >> 5, lane = tid & 31;

    // load As (combined weight) — consumed after the first sync
    for (int i = tid; i < CHK * CHK; i += 512) As[i] = g_M[i];

    // phase 0: stage x tile (fp16) + keep fp32 column in registers
    int h = tid;
    const float* xb = x + (size_t)b * TSEQ * HDIM + h;
    float xcol[CHK];
#pragma unroll
    for (int u = 0; u < CHK; ++u) {
        int pos = n * STR + u;
        xcol[u] = (pos < TSEQ) ? xb[(size_t)pos * HDIM] : 0.f;
        c2s[u * HDIM + h] = __float2half(xcol[u]);
    }
    __syncthreads();

    // phase 0b: LN1 stats per row from the staged tile
#pragma unroll
    for (int r = 0; r < 4; ++r) {
        int t = w * 4 + r;
        const uint4* rowp = (const uint4*)(c2s + t * HDIM);
        uint4 d0 = rowp[lane * 2], d1 = rowp[lane * 2 + 1];
        const __half2* p0 = (const __half2*)&d0;
        const __half2* p1 = (const __half2*)&d1;
        float sum = 0.f, sq = 0.f;
#pragma unroll
        for (int q = 0; q < 4; ++q) {
            float2 f0 = __half22float2(p0[q]);
            float2 f1 = __half22float2(p1[q]);
            sum += f0.x + f0.y + f1.x + f1.y;
            sq  += f0.x * f0.x + f0.y * f0.y + f1.x * f1.x + f1.y * f1.y;
        }
#pragma unroll
        for (int o = 16; o; o >>= 1) {
            sum += __shfl_xor_sync(0xffffffffu, sum, o);
            sq  += __shfl_xor_sync(0xffffffffu, sq,  o);
        }
        if (lane == 0) {
            float m   = sum * (1.f / HDIM);
            float var = fmaxf(sq * (1.f / HDIM) - m * m, 0.f);
            mu_s[t] = m;
            rs_s[t] = rsqrtf(var + LN_EPS);
        }
    }
    if (tid < CHK) {                      // rowM from unscaled As (As ready)
        float rm = 0.f;
        for (int u = 0; u < CHK; ++u) rm += As[tid * CHK + u];
        rowm_s[tid] = rm;
    }
    __syncthreads();                      // mu_s/rs_s ready

    for (int i = tid; i < CHK * CHK; i += 512) As[i] *= rs_s[i & (CHK - 1)];
    __syncthreads();
    if (tid < CHK) {
        float bs = 0.f;
        for (int u = 0; u < CHK; ++u) bs += As[tid * CHK + u] * mu_s[u];
        bias_s[tid] = -bs;
    }
    __syncthreads();

    {   // phase 1: matmul column
        float g1h = g1[h], b1h = b1[h];
        __half* cg = g_c2h + (size_t)tokbase * HDIM + h;
#pragma unroll 2
        for (int t = 0; t < CHK; ++t) {
            float acc = bias_s[t];
            const float4* arow = (const float4*)&As[t * CHK];
#pragma unroll
            for (int u4 = 0; u4 < CHK / 4; ++u4) {
                float4 a = arow[u4];
                acc += a.x * xcol[4 * u4 + 0];
                acc += a.y * xcol[4 * u4 + 1];
                acc += a.z * xcol[4 * u4 + 2];
                acc += a.w * xcol[4 * u4 + 3];
            }
            __half hv = __float2half(g1h * acc + b1h * rowm_s[t] + xcol[t]);
            c2s[t * HDIM + h] = hv;
            cg[(size_t)t * HDIM] = hv;
        }
    }
    __syncthreads();

    {   // phase 2: LN2 on rows; warp w handles t = w*4 .. w*4+3
        int h0 = lane * 16;
        float g2v[16], b2v[16];
#pragma unroll
        for (int j = 0; j < 16; ++j) { g2v[j] = g2[h0 + j]; b2v[j] = b2[h0 + j]; }
#pragma unroll
        for (int r = 0; r < 4; ++r) {
            int t = w * 4 + r;
            const uint4* rowp = (const uint4*)(c2s + t * HDIM);
            uint4 d0 = rowp[lane * 2], d1 = rowp[lane * 2 + 1];
            float vv[16];
            {
                const __half2* p0 = (const __half2*)&d0;
                const __half2* p1 = (const __half2*)&d1;
#pragma unroll
                for (int q = 0; q < 4; ++q) {
                    float2 f0 = __half22float2(p0[q]);
                    float2 f1 = __half22float2(p1[q]);
                    vv[2 * q] = f0.x; vv[2 * q + 1] = f0.y;
                    vv[8 + 2 * q] = f1.x; vv[8 + 2 * q + 1] = f1.y;
                }
            }
            float sum = 0.f, sq = 0.f;
#pragma unroll
            for (int j = 0; j < 16; ++j) { sum += vv[j]; sq += vv[j] * vv[j]; }
#pragma unroll
            for (int o = 16; o; o >>= 1) {
                sum += __shfl_xor_sync(0xffffffffu, sum, o);
                sq  += __shfl_xor_sync(0xffffffffu, sq,  o);
            }
            float m   = sum * (1.f / HDIM);
            float var = fmaxf(sq * (1.f / HDIM) - m * m, 0.f);
            float rs  = rsqrtf(var + LN_EPS);
            uint4 o0, o1;
            __half2* q0 = (__half2*)&o0;
            __half2* q1 = (__half2*)&o1;
#pragma unroll
            for (int q = 0; q < 4; ++q) {
                q0[q] = __floats2half2_rn(
                    (vv[2 * q]     - m) * rs * g2v[2 * q]     + b2v[2 * q],
                    (vv[2 * q + 1] - m) * rs * g2v[2 * q + 1] + b2v[2 * q + 1]);
                q1[q] = __floats2half2_rn(
                    (vv[8 + 2 * q]     - m) * rs * g2v[8 + 2 * q]     + b2v[8 + 2 * q],
                    (vv[8 + 2 * q + 1] - m) * rs * g2v[8 + 2 * q + 1] + b2v[8 + 2 * q + 1]);
            }
            uint4* vp = (uint4*)(g_vn + (size_t)(tokbase + t) * HDIM + h0);
            vp[0] = o0; vp[1] = o1;
        }
    }
}

// ---------------- single-pass fp16 HMMA GEMM, 2 stages x 2 CTAs/SM --------
// (Measured-best R10 configuration, restored verbatim.)
// MODE 0: out = __sinf(acc + bias[n]) -> fp16. MODE 1: out = acc+bias+resid fp16.
#define GSTAGES 2
#define GSTAGE_BYTES 32768           // A tile 16KB + B tile 16KB
#define GEMM_SMEM_BYTES (GSTAGES * GSTAGE_BYTES)

template <int MODE>
__global__ void __launch_bounds__(256, 2) gemm_mma(
    const __half* __restrict__ A, const __half* __restrict__ B,
    const float* __restrict__ bias, const __half* __restrict__ resid,
    __half* __restrict__ outH, int K, int N) {
    extern __shared__ __align__(128) char smem[];
    const uint32_t sb = smem_u32(smem);
    const int tid = threadIdx.x;
    const int wid = tid >> 5, lane = tid & 31;
    const int wm = wid & 1;           // M half (64 rows)
    const int wn = wid >> 1;          // N quarter (32 cols)
    const size_t mBase = (size_t)blockIdx.y * 128;
    const int    nBase = blockIdx.x * 128;
    const size_t ldbytes = (size_t)K * 2;
    const int KT = K >> 6;            // BK = 64

    auto load_stage = [&](int kt) {
        const uint32_t stg = sb + (kt & 1) * GSTAGE_BYTES;
        const size_t kOff = (size_t)kt * 128;   // 64 fp16 = 128 bytes
#pragma unroll
        for (int t = 0; t < 8; ++t) {
            const int mat = t >> 2;             // 0:A 1:B
            int cc = (t & 3) * 256 + tid;       // 0..1023
            int row = cc >> 3, c16 = cc & 7;
            uint32_t sdst = stg + mat * 16384 + tileOff128(row, c16);
            const char* src = (mat == 0)
                ? (const char*)A + (mBase + row) * ldbytes
                : (const char*)B + ((size_t)nBase + row) * ldbytes;
            CP16(sdst, src + kOff + c16 * 16);
        }
    };

    float acc[4][4][4];
#pragma unroll
    for (int i = 0; i < 4; ++i)
#pragma unroll
        for (int j = 0; j < 4; ++j)
#pragma unroll
            for (int q = 0; q < 4; ++q) acc[i][j][q] = 0.f;

    load_stage(0); CP_COMMIT();

    const int lrow = lane & 15;
    const int lcol = lane >> 4;

    for (int kt = 0; kt < KT; ++kt) {
        if (kt + 1 < KT) { load_stage(kt + 1); CP_COMMIT(); }
        if (kt + 1 < KT) asm volatile("cp.async.wait_group 1;" ::: "memory");
        else             asm volatile("cp.async.wait_group 0;" ::: "memory");
        __syncthreads();

        const uint32_t stg = sb + (kt & 1) * GSTAGE_BYTES;
        const uint32_t sA = stg, sB = stg + 16384;

#pragma unroll
        for (int ks = 0; ks < 4; ++ks) {
            const int c16 = ks * 2 + lcol;
            uint32_t ah[4][4], bh[4][2];
#pragma unroll
            for (int mi = 0; mi < 4; ++mi)
                ldsm4(ah[mi], sA + tileOff128(wm * 64 + mi * 16 + lrow, c16));
#pragma unroll
            for (int p = 0; p < 2; ++p) {
                uint32_t t4[4];
                ldsm4(t4, sB + tileOff128(wn * 32 + p * 16 + lrow, c16));
                bh[2 * p][0] = t4[0]; bh[2 * p][1] = t4[2];
                bh[2 * p + 1][0] = t4[1]; bh[2 * p + 1][1] = t4[3];
            }
#pragma unroll
            for (int mi = 0; mi < 4; ++mi)
#pragma unroll
                for (int ni = 0; ni < 4; ++ni)
                    mma16816(acc[mi][ni], ah[mi], bh[ni]);
        }
        __syncthreads();
    }

    // ---- epilogue: lane holds rows {g, g+8}, cols {c, c+1} per tile ----
    const int g = lane >> 2, cq = (lane & 3) * 2;
#pragma unroll
    for (int ni = 0; ni < 4; ++ni) {
        const int col = nBase + wn * 32 + ni * 8 + cq;
        const float b0 = bias[col], b1 = bias[col + 1];
#pragma unroll
        for (int mi = 0; mi < 4; ++mi) {
            const size_t r0 = mBase + wm * 64 + mi * 16 + g;
            const size_t r1 = r0 + 8;
            if (MODE == 0) {
                float f00 = __sinf(acc[mi][ni][0] + b0);
                float f01 = __sinf(acc[mi][ni][1] + b1);
                float f10 = __sinf(acc[mi][ni][2] + b0);
                float f11 = __sinf(acc[mi][ni][3] + b1);
                *(__half2*)(outH + r0 * N + col) = __floats2half2_rn(f00, f01);
                *(__half2*)(outH + r1 * N + col) = __floats2half2_rn(f10, f11);
            } else {
                float2 rv0 = __half22float2(*(const __half2*)(resid + r0 * N + col));
                float2 rv1 = __half22float2(*(const __half2*)(resid + r1 * N + col));
                *(__half2*)(outH + r0 * N + col) = __floats2half2_rn(
                    acc[mi][ni][0] + b0 + rv0.x, acc[mi][ni][1] + b1 + rv0.y);
                *(__half2*)(outH + r1 * N + col) = __floats2half2_rn(
                    acc[mi][ni][2] + b0 + rv1.x, acc[mi][ni][3] + b1 + rv1.y);
            }
        }
    }
}

// ---------------- gather: overlap sum + count division (fp16 oc) ----------
__global__ void gather_kernel(float* __restrict__ out) {
    size_t gid = (size_t)blockIdx.x * blockDim.x + threadIdx.x; // B*T*H/8
    int h8 = (int)(gid & (HDIM / 8 - 1));        // 0..63
    size_t rest = gid >> 6;
    int p = (int)(rest & (TSEQ - 1));
    int b = (int)(rest >> 13);
    const uint4* oc8 = (const uint4*)g_oc;       // 8 halves per uint4
    int nn = p >> 5, t = p & 31;
    size_t i0 = ((size_t)(b * NCH + nn) * CHK + t) * (HDIM / 8) + h8;
    uint4 v = oc8[i0];
    const __half2* vh = (const __half2*)&v;
    float r[8];
#pragma unroll
    for (int q = 0; q < 4; ++q) {
        float2 f = __half22float2(vh[q]);
        r[2 * q] = f.x; r[2 * q + 1] = f.y;
    }
    if (p >= STR) {
        size_t i1 = ((size_t)(b * NCH + nn - 1) * CHK + t + 32) * (HDIM / 8) + h8;
        uint4 w = oc8[i1];
        const __half2* wh = (const __half2*)&w;
#pragma unroll
        for (int q = 0; q < 4; ++q) {
            float2 f = __half22float2(wh[q]);
            r[2 * q]     = (r[2 * q]     + f.x) * 0.5f;
            r[2 * q + 1] = (r[2 * q + 1] + f.y) * 0.5f;
        }
    }
    float4* op = (float4*)(out + ((size_t)b * TSEQ + p) * HDIM + h8 * 8);
    op[0] = make_float4(r[0], r[1], r[2], r[3]);
    op[1] = make_float4(r[4], r[5], r[6], r[7]);
}

// ---------------- launch --------------------------------------------------
extern "C" void kernel_launch(void* const* d_in, const int* in_sizes, int n_in,
                              void* d_out, int out_size) {
    const float* x     = (const float*)d_in[0];
    const float* ln1_g = (const float*)d_in[1];
    const float* ln1_b = (const float*)d_in[2];
    const float* W1    = (const float*)d_in[3];
    const float* W2    = (const float*)d_in[4];
    const float* ln2_g = (const float*)d_in[5];
    const float* ln2_b = (const float*)d_in[6];
    const float* fw1   = (const float*)d_in[7];
    const float* fb1   = (const float*)d_in[8];
    const float* fw2   = (const float*)d_in[9];
    const float* fb2   = (const float*)d_in[10];
    float* out = (float*)d_out;

    __half *ocp, *c2hp, *vnp, *up, *w1p, *w2p;
    cudaGetSymbolAddress((void**)&ocp,  g_oc);
    cudaGetSymbolAddress((void**)&c2hp, g_c2h);
    cudaGetSymbolAddress((void**)&vnp,  g_vn);
    cudaGetSymbolAddress((void**)&up,   g_u);
    cudaGetSymbolAddress((void**)&w1p,  g_w1);
    cudaGetSymbolAddress((void**)&w2p,  g_w2);

    cudaFuncSetAttribute(gemm_mma<0>, cudaFuncAttributeMaxDynamicSharedMemorySize,
                         GEMM_SMEM_BYTES);
    cudaFuncSetAttribute(gemm_mma<1>, cudaFuncAttributeMaxDynamicSharedMemorySize,
                         GEMM_SMEM_BYTES);
    cudaFuncSetAttribute(chunk_mm_kernel, cudaFuncAttributeMaxDynamicSharedMemorySize,
                         CM_SMEM_BYTES);

    // 1) prep: weight transposes + combined W (LN1 now fused into chunk_mm)
    prep_kernel<<<PREP_BLKS, 256>>>(W1, W2, fw1, fw2, w1p, w2p);
    // 2) chunk matmul with fused LN1 + LN2
    chunk_mm_kernel<<<dim3(NCH, BATCH), 512, CM_SMEM_BYTES>>>(
        x, ln1_g, ln1_b, ln2_g, ln2_b);
    // 3) GEMM1: u = sin(vn @ fw1 + fb1)  [65536 x 512] x [2048 x 512]^T
    gemm_mma<0><<<dim3(EDIM / 128, TOK / 128), 256, GEMM_SMEM_BYTES>>>(
        vnp, w1p, fb1, nullptr, up, HDIM, EDIM);
    // 4) GEMM2: oc = u @ fw2 + fb2 + c2  [65536 x 2048] x [512 x 2048]^T
    gemm_mma<1><<<dim3(HDIM / 128, TOK / 128), 256, GEMM_SMEM_BYTES>>>(
        up, w2p, fb2, c2hp, ocp, EDIM, HDIM);
    // 5) overlap gather + divide
    gather_kernel<<<(size_t)BATCH * TSEQ * HDIM / 8 / 256, 256>>>(out);
}